// round 6
// baseline (speedup 1.0000x reference)
#include <cuda_runtime.h>

// QBlock W4A8: x -> qconv1x1 -> qdw3x3 -> prelu -> qconv1x1 -> qdw3x3 -> prelu -> +x
// B=16, C=64, H=W=256, fp32 NCHW.
// conv1x1 via IMMA mma.sync.m16n8k32.s8 (exact integer accumulation).

#define B_ 16
#define C_ 64
#define H_ 256
#define W_ 256
#define HW_ 65536
#define CHW_ 4194304
#define NTOT_ 67108864
#define NPOS_ 1048576

#define MAGICF 12582912.0f          // 2^23 + 2^22 : RNE integer extraction

__device__ float g_buf1[NTOT_];
__device__ float g_buf2[NTOT_];
__device__ unsigned int g_amax[4];   // 0: x, 1: y1, 2: y3, 3: y4
__device__ float g_wscale[4];
__device__ int   g_wp1[1024];        // 64 co x 16 packed int8x4 (ci)
__device__ int   g_wp2[1024];
__device__ float g_wf1[576];         // dequantized dw weights
__device__ float g_wf2[576];

// clamp+RNE in float domain; low byte of result bits == int8 (two's complement)
__device__ __forceinline__ unsigned int qbits(float v, float inv) {
    float m = v * inv;
    m = fminf(fmaxf(m, -127.0f), 127.0f);
    return __float_as_uint(m + MAGICF);
}
// clamp+RNE -> integer-valued float (no dequant scale; folded into weights)
__device__ __forceinline__ float qint(float v, float inv) {
    float m = v * inv;
    m = fminf(fmaxf(m, -127.0f), 127.0f);
    float t = m + MAGICF;
    return t - MAGICF;
}

__device__ __forceinline__ void mma_s8(int& c0, int& c1, int& c2, int& c3,
                                       int a0, int a1, int a2, int a3,
                                       int b0, int b1) {
    asm volatile(
        "mma.sync.aligned.m16n8k32.row.col.s32.s8.s8.s32 "
        "{%0,%1,%2,%3}, {%4,%5,%6,%7}, {%8,%9}, {%0,%1,%2,%3};"
        : "+r"(c0), "+r"(c1), "+r"(c2), "+r"(c3)
        : "r"(a0), "r"(a1), "r"(a2), "r"(a3), "r"(b0), "r"(b1));
}

__global__ void __launch_bounds__(256) k_wquant(const float* __restrict__ wp1,
                                                const float* __restrict__ wf1,
                                                const float* __restrict__ wp2,
                                                const float* __restrict__ wf2) {
    __shared__ float red[256];
    int tid = threadIdx.x;
    int wsel = blockIdx.x;
    if (tid == 0) g_amax[wsel] = 0u;          // init fused here (amax_x runs later)
    const float* src = (wsel == 0) ? wp1 : (wsel == 1) ? wf1 : (wsel == 2) ? wp2 : wf2;
    int n = (wsel == 0 || wsel == 2) ? 4096 : 576;

    float m = 0.f;
    for (int i = tid; i < n; i += 256) m = fmaxf(m, fabsf(src[i]));
    red[tid] = m; __syncthreads();
    for (int s = 128; s > 0; s >>= 1) {
        if (tid < s) red[tid] = fmaxf(red[tid], red[tid + s]);
        __syncthreads();
    }
    float scale = red[0] / 7.0f + 1e-12f;
    if (tid == 0) g_wscale[wsel] = scale;

    if (wsel == 0 || wsel == 2) {
        int* dst = (wsel == 0) ? g_wp1 : g_wp2;
        for (int i = tid; i < 1024; i += 256) {
            int co = i >> 4, k = i & 15;
            unsigned int packed = 0;
            #pragma unroll
            for (int j = 0; j < 4; j++) {
                float v = src[co * 64 + k * 4 + j];
                int q = __float2int_rn(v / scale);
                q = max(-7, min(7, q));
                packed |= ((unsigned int)(q & 0xFF)) << (8 * j);
            }
            dst[i] = (int)packed;
        }
    } else {
        float* dst = (wsel == 1) ? g_wf1 : g_wf2;
        for (int i = tid; i < n; i += 256) {
            float q = rintf(src[i] / scale);
            q = fmaxf(-7.f, fminf(7.f, q));
            dst[i] = q * scale;
        }
    }
}

__global__ void __launch_bounds__(256) k_amax_x(const float4* __restrict__ in) {
    __shared__ unsigned int wred[8];
    int tid = threadIdx.x;
    float m = 0.f;
    int n4 = NTOT_ / 4;
    for (int i = blockIdx.x * 256 + tid; i < n4; i += gridDim.x * 256) {
        float4 v = in[i];
        m = fmaxf(m, fmaxf(fmaxf(fabsf(v.x), fabsf(v.y)), fmaxf(fabsf(v.z), fabsf(v.w))));
    }
    unsigned int u = __reduce_max_sync(0xffffffffu, __float_as_uint(m));
    if ((tid & 31) == 0) wred[tid >> 5] = u;
    __syncthreads();
    if (tid < 8) {
        unsigned int v = wred[tid];
        #pragma unroll
        for (int s = 4; s > 0; s >>= 1) v = max(v, __shfl_down_sync(0xffu, v, s));
        if (tid == 0) atomicMax(&g_amax[0], v);
    }
}

// 1x1 conv via IMMA (R5-proven). Block = 256 threads = 8 warps = 256 pixels.
__global__ void __launch_bounds__(256) k_conv1x1(const float* __restrict__ ext_in,
                                                 int in_sel, int wp_sel,
                                                 int s_in, int s_w, int s_out) {
    __shared__ int ws[1024];
    __shared__ unsigned int wred[8];
    int tid = threadIdx.x;
    int l = tid & 31;
    const int* wpack = (wp_sel == 0) ? g_wp1 : g_wp2;
    for (int i = tid; i < 1024; i += 256) ws[i] = wpack[i];

    float amax_in = __uint_as_float(g_amax[s_in]);
    float scale_in = amax_in / 127.0f + 1e-12f;
    float inv_in = 1.0f / scale_in;
    float out_scale = scale_in * g_wscale[s_w];
    __syncthreads();

    const float* in = (in_sel == 0) ? ext_in : g_buf2;
    int p = blockIdx.x * 256 + tid;
    int b = p >> 16;
    int hw = p & 65535;
    const float* xin = in + (size_t)b * CHW_ + hw;

    int w[16];
    #pragma unroll
    for (int k = 0; k < 16; k++) {
        unsigned int q0 = qbits(xin[(size_t)(k * 4 + 0) * HW_], inv_in);
        unsigned int q1 = qbits(xin[(size_t)(k * 4 + 1) * HW_], inv_in);
        unsigned int q2 = qbits(xin[(size_t)(k * 4 + 2) * HW_], inv_in);
        unsigned int q3 = qbits(xin[(size_t)(k * 4 + 3) * HW_], inv_in);
        unsigned int lo = __byte_perm(q0, q1, 0x0040);
        unsigned int hi = __byte_perm(q2, q3, 0x0040);
        w[k] = (int)__byte_perm(lo, hi, 0x5410);
    }

    int afr[2][2][4];
    int srclo = (l >> 2);
    #pragma unroll
    for (int mt = 0; mt < 2; mt++) {
        #pragma unroll
        for (int kt = 0; kt < 2; kt++) {
            int a0 = 0, a1 = 0, a2 = 0, a3 = 0;
            #pragma unroll
            for (int j = 0; j < 4; j++) {
                int t0 = __shfl_sync(0xffffffffu, w[kt * 8 + j],     mt * 16 + srclo);
                int t1 = __shfl_sync(0xffffffffu, w[kt * 8 + j],     mt * 16 + srclo + 8);
                int t2 = __shfl_sync(0xffffffffu, w[kt * 8 + 4 + j], mt * 16 + srclo);
                int t3 = __shfl_sync(0xffffffffu, w[kt * 8 + 4 + j], mt * 16 + srclo + 8);
                if ((l & 3) == j) { a0 = t0; a1 = t1; a2 = t2; a3 = t3; }
            }
            afr[mt][kt][0] = a0; afr[mt][kt][1] = a1;
            afr[mt][kt][2] = a2; afr[mt][kt][3] = a3;
        }
    }

    int warpPix = (tid >> 5) * 32;
    int blkBase = blockIdx.x * 256;
    float m = 0.f;

    #pragma unroll
    for (int nh = 0; nh < 2; nh++) {
        int cfr[2][4][4];
        #pragma unroll
        for (int mt = 0; mt < 2; mt++)
            #pragma unroll
            for (int nt = 0; nt < 4; nt++) {
                cfr[mt][nt][0] = 0; cfr[mt][nt][1] = 0;
                cfr[mt][nt][2] = 0; cfr[mt][nt][3] = 0;
            }

        #pragma unroll
        for (int nt = 0; nt < 4; nt++) {
            int co = nh * 32 + nt * 8 + (l >> 2);
            #pragma unroll
            for (int kt = 0; kt < 2; kt++) {
                int b0 = ws[co * 16 + kt * 8 + (l & 3)];
                int b1 = ws[co * 16 + kt * 8 + 4 + (l & 3)];
                #pragma unroll
                for (int mt = 0; mt < 2; mt++) {
                    mma_s8(cfr[mt][nt][0], cfr[mt][nt][1], cfr[mt][nt][2], cfr[mt][nt][3],
                           afr[mt][kt][0], afr[mt][kt][1], afr[mt][kt][2], afr[mt][kt][3],
                           b0, b1);
                }
            }
        }

        #pragma unroll
        for (int mt = 0; mt < 2; mt++) {
            int pix0 = blkBase + warpPix + mt * 16 + (l >> 2);
            int hw0 = pix0 & 65535;
            #pragma unroll
            for (int nt = 0; nt < 4; nt++) {
                int co = nh * 32 + nt * 8 + 2 * (l & 3);
                float* base0 = g_buf1 + (size_t)b * CHW_ + (size_t)co * HW_;
                float y0 = (float)cfr[mt][nt][0] * out_scale;
                float y1 = (float)cfr[mt][nt][1] * out_scale;
                float y2 = (float)cfr[mt][nt][2] * out_scale;
                float y3 = (float)cfr[mt][nt][3] * out_scale;
                base0[hw0]            = y0;
                base0[HW_ + hw0]      = y1;
                base0[hw0 + 8]        = y2;
                base0[HW_ + hw0 + 8]  = y3;
                m = fmaxf(m, fmaxf(fmaxf(fabsf(y0), fabsf(y1)), fmaxf(fabsf(y2), fabsf(y3))));
            }
        }
    }

    unsigned int u = __reduce_max_sync(0xffffffffu, __float_as_uint(m));
    if ((tid & 31) == 0) wred[tid >> 5] = u;
    __syncthreads();
    if (tid < 8) {
        unsigned int v = wred[tid];
        #pragma unroll
        for (int s = 4; s > 0; s >>= 1) v = max(v, __shfl_down_sync(0xffu, v, s));
        if (tid == 0) atomicMax(&g_amax[s_out], v);
    }
}

// Depthwise 3x3 (pad 1) + PReLU [+ residual].
// Tile: W=256 x 32 rows, 512 threads (2 row-halves of 16). scale folded into
// weights; smem holds integer-valued floats; aligned float4 smem stores with
// pad cols 256 (right halo) / 257 (left halo), both zero.
#define DWROWS 32
__global__ void __launch_bounds__(512) k_dw3x3(float* __restrict__ ext_out,
                                               const float* __restrict__ resid,
                                               const float* __restrict__ alpha,
                                               int wf_sel, int s_in, int s_out) {
    __shared__ float sh[DWROWS + 2][260];    // data cols 0..255; 256,257 = zero pads
    __shared__ unsigned int wred[16];

    int bc = blockIdx.y;                      // b*64 + c
    int ch = bc & 63;
    int tid = threadIdx.x;
    int y0 = blockIdx.x * DWROWS;

    float amax_in = __uint_as_float(g_amax[s_in]);
    float scale_in = amax_in / 127.0f + 1e-12f;
    float inv_in = 1.0f / scale_in;

    const float* wf = (wf_sel == 0) ? g_wf1 : g_wf2;
    float w0 = wf[ch * 9 + 0] * scale_in, w1 = wf[ch * 9 + 1] * scale_in, w2 = wf[ch * 9 + 2] * scale_in;
    float w3 = wf[ch * 9 + 3] * scale_in, w4 = wf[ch * 9 + 4] * scale_in, w5 = wf[ch * 9 + 5] * scale_in;
    float w6 = wf[ch * 9 + 6] * scale_in, w7 = wf[ch * 9 + 7] * scale_in, w8 = wf[ch * 9 + 8] * scale_in;
    float a = alpha[ch];

    const float4* plane4 = (const float4*)(g_buf1 + (size_t)bc * HW_);

    if (tid < DWROWS + 2) { sh[tid][256] = 0.f; sh[tid][257] = 0.f; }

    // load (DWROWS+2) rows x 64 float4; quantize to integer-valued floats
    for (int i = tid; i < (DWROWS + 2) * 64; i += 512) {
        int r = i >> 6, c4 = i & 63;
        int gy = y0 + r - 1;
        float4 o;
        o.x = 0.f; o.y = 0.f; o.z = 0.f; o.w = 0.f;
        if (gy >= 0 && gy < H_) {
            float4 v = plane4[gy * 64 + c4];
            o.x = qint(v.x, inv_in);
            o.y = qint(v.y, inv_in);
            o.z = qint(v.z, inv_in);
            o.w = qint(v.w, inv_in);
        }
        *(float4*)&sh[r][c4 * 4] = o;
    }
    __syncthreads();

    int col = tid & 255;                      // output column 0..255
    int half = tid >> 8;                      // 0 or 1 -> rows half*16 .. +15
    int r0 = half * 16;
    int lcol = (col == 0) ? 257 : col - 1;    // left neighbor (257 = zero pad)
    int rcol = col + 1;                       // col=255 -> 256 = zero pad

    float t00 = sh[r0][lcol], t01 = sh[r0][col], t02 = sh[r0][rcol];
    float t10 = sh[r0 + 1][lcol], t11 = sh[r0 + 1][col], t12 = sh[r0 + 1][rcol];

    float* out = ext_out ? ext_out : g_buf2;
    size_t obase = (size_t)bc * HW_ + (size_t)(y0 + r0) * W_ + col;
    float m = 0.f;

    #pragma unroll
    for (int r = 0; r < 16; r++) {
        float t20 = sh[r0 + r + 2][lcol], t21 = sh[r0 + r + 2][col], t22 = sh[r0 + r + 2][rcol];
        float acc = t00 * w0;
        acc = fmaf(t01, w1, acc); acc = fmaf(t02, w2, acc);
        acc = fmaf(t10, w3, acc); acc = fmaf(t11, w4, acc);
        acc = fmaf(t12, w5, acc); acc = fmaf(t20, w6, acc);
        acc = fmaf(t21, w7, acc); acc = fmaf(t22, w8, acc);
        float v = fmaxf(acc, 0.f) + a * fminf(acc, 0.f);   // PReLU
        size_t oidx = obase + (size_t)r * W_;
        if (resid) v += resid[oidx];
        out[oidx] = v;
        m = fmaxf(m, fabsf(v));
        t00 = t10; t01 = t11; t02 = t12;
        t10 = t20; t11 = t21; t12 = t22;
    }

    if (s_out >= 0) {
        unsigned int u = __reduce_max_sync(0xffffffffu, __float_as_uint(m));
        if ((tid & 31) == 0) wred[tid >> 5] = u;
        __syncthreads();
        if (tid < 16) {
            unsigned int v = wred[tid];
            #pragma unroll
            for (int s = 8; s > 0; s >>= 1) v = max(v, __shfl_down_sync(0xffffu, v, s));
            if (tid == 0) atomicMax(&g_amax[s_out], v);
        }
    }
}

extern "C" void kernel_launch(void* const* d_in, const int* in_sizes, int n_in,
                              void* d_out, int out_size) {
    const float* x   = (const float*)d_in[0];
    const float* wp1 = (const float*)d_in[1];
    const float* wf1 = (const float*)d_in[2];
    const float* wp2 = (const float*)d_in[3];
    const float* wf2 = (const float*)d_in[4];
    const float* a1  = (const float*)d_in[5];
    const float* a2  = (const float*)d_in[6];
    float* out = (float*)d_out;

    dim3 dwGrid(H_ / DWROWS, B_ * C_);

    k_wquant<<<4, 256>>>(wp1, wf1, wp2, wf2);   // also zeroes g_amax
    k_amax_x<<<8192, 256>>>((const float4*)x);

    k_conv1x1<<<NPOS_ / 256, 256>>>(x, 0, 0, /*s_in=*/0, /*s_w=*/0, /*s_out=*/1);
    k_dw3x3<<<dwGrid, 512>>>(nullptr, nullptr, a1, 0, /*s_in=*/1, /*s_out=*/2);
    k_conv1x1<<<NPOS_ / 256, 256>>>(x, 1, 1, /*s_in=*/2, /*s_w=*/2, /*s_out=*/3);
    k_dw3x3<<<dwGrid, 512>>>(out, x, a2, 1, /*s_in=*/3, /*s_out=*/-1);
}

// round 7
// speedup vs baseline: 1.0538x; 1.0538x over previous
#include <cuda_runtime.h>

// QBlock W4A8: x -> qconv1x1 -> qdw3x3 -> prelu -> qconv1x1 -> qdw3x3 -> prelu -> +x
// B=16, C=64, H=W=256, fp32 NCHW.
// conv1x1 via IMMA mma.sync.m16n8k32.s8; conv outputs stored as int16 acc
// (|acc| <= 64*127*7 = 56896 < 2^15, exact). dw reconstructs y = acc*out_scale.

#define B_ 16
#define C_ 64
#define H_ 256
#define W_ 256
#define HW_ 65536
#define CHW_ 4194304
#define NTOT_ 67108864
#define NPOS_ 1048576

#define MAGICF 12582912.0f          // 2^23 + 2^22 : RNE integer extraction

__device__ short g_sbuf[NTOT_];      // conv -> dw (int16 accumulators)
__device__ float g_fbuf[NTOT_];      // dw1 -> conv2 (float)
__device__ unsigned int g_amax[4];   // 0: x, 1: y1, 2: y3, 3: y4
__device__ float g_wscale[4];        // wp1, wf1, wp2, wf2
__device__ int   g_wp1[1024];        // 64 co x 16 packed int8x4 (ci)
__device__ int   g_wp2[1024];
__device__ float g_wf1[576];         // dequantized dw weights
__device__ float g_wf2[576];

// clamp+RNE in float domain; low byte of result bits == int8 (two's complement)
__device__ __forceinline__ unsigned int qbits(float v, float inv) {
    float m = v * inv;
    m = fminf(fmaxf(m, -127.0f), 127.0f);
    return __float_as_uint(m + MAGICF);
}
// clamp+RNE -> integer-valued float (dequant scale folded into dw weights)
__device__ __forceinline__ float qintm(float m) {
    m = fminf(fmaxf(m, -127.0f), 127.0f);
    float t = m + MAGICF;
    return t - MAGICF;
}

__device__ __forceinline__ void mma_s8(int& c0, int& c1, int& c2, int& c3,
                                       int a0, int a1, int a2, int a3,
                                       int b0, int b1) {
    asm volatile(
        "mma.sync.aligned.m16n8k32.row.col.s32.s8.s8.s32 "
        "{%0,%1,%2,%3}, {%4,%5,%6,%7}, {%8,%9}, {%0,%1,%2,%3};"
        : "+r"(c0), "+r"(c1), "+r"(c2), "+r"(c3)
        : "r"(a0), "r"(a1), "r"(a2), "r"(a3), "r"(b0), "r"(b1));
}

__global__ void __launch_bounds__(256) k_wquant(const float* __restrict__ wp1,
                                                const float* __restrict__ wf1,
                                                const float* __restrict__ wp2,
                                                const float* __restrict__ wf2) {
    __shared__ float red[256];
    int tid = threadIdx.x;
    int wsel = blockIdx.x;
    if (tid == 0) g_amax[wsel] = 0u;          // init fused (amax_x runs later)
    const float* src = (wsel == 0) ? wp1 : (wsel == 1) ? wf1 : (wsel == 2) ? wp2 : wf2;
    int n = (wsel == 0 || wsel == 2) ? 4096 : 576;

    float m = 0.f;
    for (int i = tid; i < n; i += 256) m = fmaxf(m, fabsf(src[i]));
    red[tid] = m; __syncthreads();
    for (int s = 128; s > 0; s >>= 1) {
        if (tid < s) red[tid] = fmaxf(red[tid], red[tid + s]);
        __syncthreads();
    }
    float scale = red[0] / 7.0f + 1e-12f;
    if (tid == 0) g_wscale[wsel] = scale;

    if (wsel == 0 || wsel == 2) {
        int* dst = (wsel == 0) ? g_wp1 : g_wp2;
        for (int i = tid; i < 1024; i += 256) {
            int co = i >> 4, k = i & 15;
            unsigned int packed = 0;
            #pragma unroll
            for (int j = 0; j < 4; j++) {
                float v = src[co * 64 + k * 4 + j];
                int q = __float2int_rn(v / scale);
                q = max(-7, min(7, q));
                packed |= ((unsigned int)(q & 0xFF)) << (8 * j);
            }
            dst[i] = (int)packed;
        }
    } else {
        float* dst = (wsel == 1) ? g_wf1 : g_wf2;
        for (int i = tid; i < n; i += 256) {
            float q = rintf(src[i] / scale);
            q = fmaxf(-7.f, fminf(7.f, q));
            dst[i] = q * scale;
        }
    }
}

__global__ void __launch_bounds__(256) k_amax_x(const float4* __restrict__ in) {
    __shared__ unsigned int wred[8];
    int tid = threadIdx.x;
    float m = 0.f;
    int n4 = NTOT_ / 4;
    for (int i = blockIdx.x * 256 + tid; i < n4; i += gridDim.x * 256) {
        float4 v = in[i];
        m = fmaxf(m, fmaxf(fmaxf(fabsf(v.x), fabsf(v.y)), fmaxf(fabsf(v.z), fabsf(v.w))));
    }
    unsigned int u = __reduce_max_sync(0xffffffffu, __float_as_uint(m));
    if ((tid & 31) == 0) wred[tid >> 5] = u;
    __syncthreads();
    if (tid < 8) {
        unsigned int v = wred[tid];
        #pragma unroll
        for (int s = 4; s > 0; s >>= 1) v = max(v, __shfl_down_sync(0xffu, v, s));
        if (tid == 0) atomicMax(&g_amax[0], v);
    }
}

// 1x1 conv via IMMA. Block = 256 threads = 8 warps = 256 pixels.
// Output: int16 accumulators -> g_sbuf. amax of float y -> g_amax[s_out].
__global__ void __launch_bounds__(256) k_conv1x1(const float* __restrict__ ext_in,
                                                 int in_sel, int wp_sel,
                                                 int s_in, int s_w, int s_out) {
    __shared__ int ws[1024];
    __shared__ unsigned int wred[8];
    int tid = threadIdx.x;
    int l = tid & 31;
    const int* wpack = (wp_sel == 0) ? g_wp1 : g_wp2;
    for (int i = tid; i < 1024; i += 256) ws[i] = wpack[i];

    float amax_in = __uint_as_float(g_amax[s_in]);
    float scale_in = amax_in / 127.0f + 1e-12f;
    float inv_in = 1.0f / scale_in;
    float out_scale = scale_in * g_wscale[s_w];
    __syncthreads();

    const float* in = (in_sel == 0) ? ext_in : g_fbuf;
    int p = blockIdx.x * 256 + tid;
    int b = p >> 16;
    int hw = p & 65535;
    const float* xin = in + (size_t)b * CHW_ + hw;

    int w[16];
    #pragma unroll
    for (int k = 0; k < 16; k++) {
        unsigned int q0 = qbits(xin[(size_t)(k * 4 + 0) * HW_], inv_in);
        unsigned int q1 = qbits(xin[(size_t)(k * 4 + 1) * HW_], inv_in);
        unsigned int q2 = qbits(xin[(size_t)(k * 4 + 2) * HW_], inv_in);
        unsigned int q3 = qbits(xin[(size_t)(k * 4 + 3) * HW_], inv_in);
        unsigned int lo = __byte_perm(q0, q1, 0x0040);
        unsigned int hi = __byte_perm(q2, q3, 0x0040);
        w[k] = (int)__byte_perm(lo, hi, 0x5410);
    }

    int afr[2][2][4];
    int srclo = (l >> 2);
    #pragma unroll
    for (int mt = 0; mt < 2; mt++) {
        #pragma unroll
        for (int kt = 0; kt < 2; kt++) {
            int a0 = 0, a1 = 0, a2 = 0, a3 = 0;
            #pragma unroll
            for (int j = 0; j < 4; j++) {
                int t0 = __shfl_sync(0xffffffffu, w[kt * 8 + j],     mt * 16 + srclo);
                int t1 = __shfl_sync(0xffffffffu, w[kt * 8 + j],     mt * 16 + srclo + 8);
                int t2 = __shfl_sync(0xffffffffu, w[kt * 8 + 4 + j], mt * 16 + srclo);
                int t3 = __shfl_sync(0xffffffffu, w[kt * 8 + 4 + j], mt * 16 + srclo + 8);
                if ((l & 3) == j) { a0 = t0; a1 = t1; a2 = t2; a3 = t3; }
            }
            afr[mt][kt][0] = a0; afr[mt][kt][1] = a1;
            afr[mt][kt][2] = a2; afr[mt][kt][3] = a3;
        }
    }

    int warpPix = (tid >> 5) * 32;
    int blkBase = blockIdx.x * 256;
    float m = 0.f;

    #pragma unroll
    for (int nh = 0; nh < 2; nh++) {
        int cfr[2][4][4];
        #pragma unroll
        for (int mt = 0; mt < 2; mt++)
            #pragma unroll
            for (int nt = 0; nt < 4; nt++) {
                cfr[mt][nt][0] = 0; cfr[mt][nt][1] = 0;
                cfr[mt][nt][2] = 0; cfr[mt][nt][3] = 0;
            }

        #pragma unroll
        for (int nt = 0; nt < 4; nt++) {
            int co = nh * 32 + nt * 8 + (l >> 2);
            #pragma unroll
            for (int kt = 0; kt < 2; kt++) {
                int b0 = ws[co * 16 + kt * 8 + (l & 3)];
                int b1 = ws[co * 16 + kt * 8 + 4 + (l & 3)];
                #pragma unroll
                for (int mt = 0; mt < 2; mt++) {
                    mma_s8(cfr[mt][nt][0], cfr[mt][nt][1], cfr[mt][nt][2], cfr[mt][nt][3],
                           afr[mt][kt][0], afr[mt][kt][1], afr[mt][kt][2], afr[mt][kt][3],
                           b0, b1);
                }
            }
        }

        #pragma unroll
        for (int mt = 0; mt < 2; mt++) {
            int pix0 = blkBase + warpPix + mt * 16 + (l >> 2);
            int hw0 = pix0 & 65535;
            #pragma unroll
            for (int nt = 0; nt < 4; nt++) {
                int co = nh * 32 + nt * 8 + 2 * (l & 3);
                short* base0 = g_sbuf + (size_t)b * CHW_ + (size_t)co * HW_;
                int a0 = cfr[mt][nt][0], a1 = cfr[mt][nt][1];
                int a2 = cfr[mt][nt][2], a3 = cfr[mt][nt][3];
                base0[hw0]            = (short)a0;
                base0[HW_ + hw0]      = (short)a1;
                base0[hw0 + 8]        = (short)a2;
                base0[HW_ + hw0 + 8]  = (short)a3;
                float y0 = (float)a0 * out_scale;
                float y1 = (float)a1 * out_scale;
                float y2 = (float)a2 * out_scale;
                float y3 = (float)a3 * out_scale;
                m = fmaxf(m, fmaxf(fmaxf(fabsf(y0), fabsf(y1)), fmaxf(fabsf(y2), fabsf(y3))));
            }
        }
    }

    unsigned int u = __reduce_max_sync(0xffffffffu, __float_as_uint(m));
    if ((tid & 31) == 0) wred[tid >> 5] = u;
    __syncthreads();
    if (tid < 8) {
        unsigned int v = wred[tid];
        #pragma unroll
        for (int s = 4; s > 0; s >>= 1) v = max(v, __shfl_down_sync(0xffu, v, s));
        if (tid == 0) atomicMax(&g_amax[s_out], v);
    }
}

// Depthwise 3x3 (pad 1) + PReLU [+ residual]. Input: g_sbuf int16 accs.
// y = (float)acc * k_prev  (k_prev = conv's out_scale, recomputed bit-identically),
// then quantize; scale folded into weights. Tile: W=256 x 32 rows, 512 threads.
#define DWROWS 32
__global__ void __launch_bounds__(512) k_dw3x3(float* __restrict__ ext_out,
                                               const float* __restrict__ resid,
                                               const float* __restrict__ alpha,
                                               int wf_sel, int sc_prev, int w_prev,
                                               int s_in, int s_out) {
    __shared__ float sh[DWROWS + 2][260];    // data cols 0..255; 256,257 zero pads
    __shared__ unsigned int wred[16];

    int bc = blockIdx.y;                      // b*64 + c
    int ch = bc & 63;
    int tid = threadIdx.x;
    int y0 = blockIdx.x * DWROWS;

    // reconstruct conv's out_scale (same expression, same inputs -> identical fp32)
    float k_prev = (__uint_as_float(g_amax[sc_prev]) / 127.0f + 1e-12f) * g_wscale[w_prev];
    float amax_in = __uint_as_float(g_amax[s_in]);
    float scale_in = amax_in / 127.0f + 1e-12f;
    float inv_in = 1.0f / scale_in;

    const float* wf = (wf_sel == 0) ? g_wf1 : g_wf2;
    float w0 = wf[ch * 9 + 0] * scale_in, w1 = wf[ch * 9 + 1] * scale_in, w2 = wf[ch * 9 + 2] * scale_in;
    float w3 = wf[ch * 9 + 3] * scale_in, w4 = wf[ch * 9 + 4] * scale_in, w5 = wf[ch * 9 + 5] * scale_in;
    float w6 = wf[ch * 9 + 6] * scale_in, w7 = wf[ch * 9 + 7] * scale_in, w8 = wf[ch * 9 + 8] * scale_in;
    float a = alpha[ch];

    const short4* plane = (const short4*)(g_sbuf + (size_t)bc * HW_);

    if (tid < DWROWS + 2) { sh[tid][256] = 0.f; sh[tid][257] = 0.f; }

    // load (DWROWS+2) rows x 64 short4; y=acc*k_prev; quantize to int-valued floats
    for (int i = tid; i < (DWROWS + 2) * 64; i += 512) {
        int r = i >> 6, c4 = i & 63;
        int gy = y0 + r - 1;
        float4 o;
        o.x = 0.f; o.y = 0.f; o.z = 0.f; o.w = 0.f;
        if (gy >= 0 && gy < H_) {
            short4 v = plane[gy * 64 + c4];
            o.x = qintm(((float)v.x * k_prev) * inv_in);
            o.y = qintm(((float)v.y * k_prev) * inv_in);
            o.z = qintm(((float)v.z * k_prev) * inv_in);
            o.w = qintm(((float)v.w * k_prev) * inv_in);
        }
        *(float4*)&sh[r][c4 * 4] = o;
    }
    __syncthreads();

    int col = tid & 255;                      // output column 0..255
    int half = tid >> 8;                      // 0 or 1 -> rows half*16 .. +15
    int r0 = half * 16;
    int lcol = (col == 0) ? 257 : col - 1;    // left neighbor (257 = zero pad)
    int rcol = col + 1;                       // col=255 -> 256 = zero pad

    float t00 = sh[r0][lcol], t01 = sh[r0][col], t02 = sh[r0][rcol];
    float t10 = sh[r0 + 1][lcol], t11 = sh[r0 + 1][col], t12 = sh[r0 + 1][rcol];

    float* out = ext_out ? ext_out : g_fbuf;
    size_t obase = (size_t)bc * HW_ + (size_t)(y0 + r0) * W_ + col;
    float m = 0.f;

    #pragma unroll
    for (int r = 0; r < 16; r++) {
        float t20 = sh[r0 + r + 2][lcol], t21 = sh[r0 + r + 2][col], t22 = sh[r0 + r + 2][rcol];
        float acc = t00 * w0;
        acc = fmaf(t01, w1, acc); acc = fmaf(t02, w2, acc);
        acc = fmaf(t10, w3, acc); acc = fmaf(t11, w4, acc);
        acc = fmaf(t12, w5, acc); acc = fmaf(t20, w6, acc);
        acc = fmaf(t21, w7, acc); acc = fmaf(t22, w8, acc);
        float v = fmaxf(acc, 0.f) + a * fminf(acc, 0.f);   // PReLU
        size_t oidx = obase + (size_t)r * W_;
        if (resid) v += resid[oidx];
        out[oidx] = v;
        m = fmaxf(m, fabsf(v));
        t00 = t10; t01 = t11; t02 = t12;
        t10 = t20; t11 = t21; t12 = t22;
    }

    if (s_out >= 0) {
        unsigned int u = __reduce_max_sync(0xffffffffu, __float_as_uint(m));
        if ((tid & 31) == 0) wred[tid >> 5] = u;
        __syncthreads();
        if (tid < 16) {
            unsigned int v = wred[tid];
            #pragma unroll
            for (int s = 8; s > 0; s >>= 1) v = max(v, __shfl_down_sync(0xffffu, v, s));
            if (tid == 0) atomicMax(&g_amax[s_out], v);
        }
    }
}

extern "C" void kernel_launch(void* const* d_in, const int* in_sizes, int n_in,
                              void* d_out, int out_size) {
    const float* x   = (const float*)d_in[0];
    const float* wp1 = (const float*)d_in[1];
    const float* wf1 = (const float*)d_in[2];
    const float* wp2 = (const float*)d_in[3];
    const float* wf2 = (const float*)d_in[4];
    const float* a1  = (const float*)d_in[5];
    const float* a2  = (const float*)d_in[6];
    float* out = (float*)d_out;

    dim3 dwGrid(H_ / DWROWS, B_ * C_);

    k_wquant<<<4, 256>>>(wp1, wf1, wp2, wf2);   // also zeroes g_amax
    k_amax_x<<<8192, 256>>>((const float4*)x);

    // y1 acc -> g_sbuf (int16), amax(y1) -> 1
    k_conv1x1<<<NPOS_ / 256, 256>>>(x, 0, 0, /*s_in=*/0, /*s_w=*/0, /*s_out=*/1);
    // y3 -> g_fbuf (float), amax(y3) -> 2
    k_dw3x3<<<dwGrid, 512>>>(nullptr, nullptr, a1, /*wf=*/0,
                             /*sc_prev=*/0, /*w_prev=*/0, /*s_in=*/1, /*s_out=*/2);
    // y4 acc -> g_sbuf (int16), amax(y4) -> 3
    k_conv1x1<<<NPOS_ / 256, 256>>>(x, 1, 1, /*s_in=*/2, /*s_w=*/2, /*s_out=*/3);
    // out = prelu(dw(q(y4))) + x
    k_dw3x3<<<dwGrid, 512>>>(out, x, a2, /*wf=*/1,
                             /*sc_prev=*/2, /*w_prev=*/2, /*s_in=*/3, /*s_out=*/-1);
}